// round 5
// baseline (speedup 1.0000x reference)
#include <cuda_runtime.h>

// Problem constants (fixed by the reference setup_inputs)
#define BB 64
#define SS 2048
#define DD 768
#define DD4 192          // DD / 4 (float4)
#define POOL 32
#define LL 8
#define TOPK 4
#define PROMPT_ROWS 41   // L + TOPK*L + 1
#define ROWS_OUT 2089    // PROMPT_ROWS + SS
#define SCHUNK 64
#define NCHUNK 32        // SS / SCHUNK -> grid 2048 (measured-best config)
#define EPSV 1e-12f

// Scratch (no allocations allowed in kernel_launch)
__device__ float g_dot[NCHUNK * BB * POOL];     // 256 KB: per-chunk key dots

// ---------------------------------------------------------------------------
// Kernel 1: stream-copy x -> out tail; each block dots its 768-dim partial
// sum against all 32 keys and emits 32 floats (no 6.3MB partial stream).
// grid = (NCHUNK, BB) = 2048 blocks, block = 192 threads.
// ---------------------------------------------------------------------------
__global__ void k_copy_dot(const float4* __restrict__ x,
                           const float* __restrict__ keys,
                           float4* __restrict__ out) {
    __shared__ float q_s[DD];

    const int b     = blockIdx.y;
    const int chunk = blockIdx.x;
    const int t     = threadIdx.x;                   // 0..191

    const float4* xp = x   + ((size_t)b * SS + (size_t)chunk * SCHUNK) * DD4 + t;
    float4*       op = out + ((size_t)b * ROWS_OUT + PROMPT_ROWS
                              + (size_t)chunk * SCHUNK) * DD4 + t;

    float4 acc = make_float4(0.f, 0.f, 0.f, 0.f);
    #pragma unroll 8
    for (int s = 0; s < SCHUNK; s++) {
        float4 v = xp[(size_t)s * DD4];
        op[(size_t)s * DD4] = v;
        acc.x += v.x; acc.y += v.y; acc.z += v.z; acc.w += v.w;
    }
    ((float4*)q_s)[t] = acc;        // thread t owns dims [4t, 4t+3]
    __syncthreads();

    // 6 warps cover 32 pools (p = w + 6*i); lane-strided coalesced key reads.
    const int w = t >> 5, lane = t & 31;
    float* dout = &g_dot[((size_t)chunk * BB + b) * POOL];
    #pragma unroll
    for (int i = 0; i < 6; i++) {
        const int p = w + 6 * i;
        if (p < POOL) {
            float a = 0.f;
            #pragma unroll
            for (int d = lane; d < DD; d += 32)
                a += q_s[d] * keys[(size_t)p * DD + d];
            #pragma unroll
            for (int o = 16; o > 0; o >>= 1)
                a += __shfl_xor_sync(0xffffffffu, a, o);
            if (lane == 0) dout[p] = a;
        }
    }
}

// ---------------------------------------------------------------------------
// Kernel 2: per batch — key norms, sims from chunk dots, top-4, and write
// all 41 prompt rows. grid = BB, block = 1024.
// ---------------------------------------------------------------------------
__global__ void k_topk_prompts(const float* __restrict__ keys,
                               const float4* __restrict__ gp,
                               const float4* __restrict__ ep,
                               const float4* __restrict__ cls,
                               const int* __restrict__ task_id,
                               float4* __restrict__ out) {
    __shared__ float kk_s[POOL];
    __shared__ float sims[POOL];
    __shared__ int   topidx[TOPK];

    const int b = blockIdx.x;
    const int t = threadIdx.x;
    const int w = t >> 5, lane = t & 31;

    // Key squared norms: warps 0..7, 4 pools each (L2-resident, 96 KB)
    if (w < 8) {
        #pragma unroll
        for (int pp = 0; pp < 4; pp++) {
            const int p = w * 4 + pp;
            float a = 0.f;
            #pragma unroll
            for (int d = lane; d < DD; d += 32) {
                const float k = keys[(size_t)p * DD + d];
                a += k * k;
            }
            #pragma unroll
            for (int o = 16; o > 0; o >>= 1)
                a += __shfl_xor_sync(0xffffffffu, a, o);
            if (lane == 0) kk_s[p] = a;
        }
    }
    __syncthreads();

    // Sims: thread p sums the 32 chunk dots (deterministic order), scales
    // by rsqrt(||k||^2+eps). The rsqrt(||q||^2+eps) factor is a positive
    // per-batch constant and cannot change the top-k ordering.
    if (t < POOL) {
        float s = 0.f;
        #pragma unroll
        for (int c = 0; c < NCHUNK; c++)
            s += g_dot[((size_t)c * BB + b) * POOL + t];
        sims[t] = s * rsqrtf(kk_s[t] + EPSV);
    }
    __syncthreads();

    // Serial top-4 (32 elems): strict > keeps lowest index on ties
    if (t == 0) {
        unsigned used = 0;
        #pragma unroll
        for (int k = 0; k < TOPK; k++) {
            float best = -3.402823e38f; int bi = 0;
            for (int p = 0; p < POOL; p++) {
                if (!((used >> p) & 1u) && sims[p] > best) { best = sims[p]; bi = p; }
            }
            used |= 1u << bi;
            topidx[k] = bi;
        }
    }
    __syncthreads();

    // Write all 41 prompt rows for this batch (7872 float4, ~8/thread)
    const int task = task_id[0];
    float4* ob = out + (size_t)b * ROWS_OUT * DD4;
    for (int idx = t; idx < PROMPT_ROWS * DD4; idx += 1024) {
        const int r  = idx / DD4;
        const int d4 = idx - r * DD4;
        const float4* src;
        if (r < LL) {
            src = gp + ((size_t)task * LL + r) * DD4;
        } else if (r < LL + TOPK * LL) {
            const int rr = r - LL;
            src = ep + ((size_t)topidx[rr >> 3] * LL + (rr & 7)) * DD4;
        } else {
            src = cls;
        }
        ob[(size_t)r * DD4 + d4] = src[d4];
    }
}

// ---------------------------------------------------------------------------
extern "C" void kernel_launch(void* const* d_in, const int* in_sizes, int n_in,
                              void* d_out, int out_size) {
    const float4* x   = (const float4*)d_in[0];   // [64,2048,768]
    const float4* gp  = (const float4*)d_in[1];   // [10,8,768]
    const float4* ep  = (const float4*)d_in[2];   // [32,8,768]
    const float*  key = (const float*) d_in[3];   // [32,768]
    const float4* cls = (const float4*)d_in[4];   // [1,1,768]
    const int*    tid = (const int*)   d_in[5];   // scalar task_id
    float4* out = (float4*)d_out;

    k_copy_dot<<<dim3(NCHUNK, BB), 192>>>(x, key, out);
    k_topk_prompts<<<BB, 1024>>>(key, gp, ep, cls, tid, out);
}

// round 6
// speedup vs baseline: 1.0186x; 1.0186x over previous
#include <cuda_runtime.h>

// Problem constants (fixed by the reference setup_inputs)
#define BB 64
#define SS 2048
#define DD 768
#define DD4 192          // DD / 4 (float4)
#define POOL 32
#define LL 8
#define TOPK 4
#define PROMPT_ROWS 41   // L + TOPK*L + 1
#define ROWS_OUT 2089    // PROMPT_ROWS + SS
#define SCHUNK 64
#define NCHUNK 32        // SS / SCHUNK -> grid 2048 (measured-best config)
#define EPSV 1e-12f

// Scratch (no allocations allowed in kernel_launch)
__device__ float g_partial[NCHUNK * BB * DD];   // ~6.3 MB
__device__ int   g_topidx[BB * TOPK];

// ---------------------------------------------------------------------------
// Kernel 1: stream-copy x -> out tail + per-(chunk,b,d) partial sums.
// Hot loop identical to the measured-best R1 kernel. Blocks with chunk<9
// additionally write one topk-independent prompt row (g rows 0-7, cls row 40).
// grid = (NCHUNK, BB) = 2048 blocks, block = 192 threads.
// ---------------------------------------------------------------------------
__global__ void k_copy_reduce(const float4* __restrict__ x,
                              const float4* __restrict__ gp,
                              const float4* __restrict__ cls,
                              const int* __restrict__ task_id,
                              float4* __restrict__ out) {
    const int b     = blockIdx.y;
    const int chunk = blockIdx.x;
    const int t     = threadIdx.x;                   // 0..191

    const float4* xp = x   + ((size_t)b * SS + (size_t)chunk * SCHUNK) * DD4 + t;
    float4*       op = out + ((size_t)b * ROWS_OUT + PROMPT_ROWS
                              + (size_t)chunk * SCHUNK) * DD4 + t;

    float4 acc = make_float4(0.f, 0.f, 0.f, 0.f);
    #pragma unroll 8
    for (int s = 0; s < SCHUNK; s++) {
        float4 v = xp[(size_t)s * DD4];
        op[(size_t)s * DD4] = v;
        acc.x += v.x; acc.y += v.y; acc.z += v.z; acc.w += v.w;
    }
    ((float4*)g_partial)[((size_t)chunk * BB + b) * DD4 + t] = acc;

    // topk-independent prompt rows: chunk 0..7 -> g row; chunk 8 -> cls row
    if (chunk < 9) {
        const float4* src = (chunk < LL)
            ? gp + ((size_t)task_id[0] * LL + chunk) * DD4
            : cls;
        const int r = (chunk < LL) ? chunk : (PROMPT_ROWS - 1);
        out[((size_t)b * ROWS_OUT + r) * DD4 + t] = src[t];
    }
}

// ---------------------------------------------------------------------------
// Kernel 2: per batch — reduce partials (no q-norm needed: positive per-batch
// scale can't change ordering), sims vs keys, top-4.  grid = BB, block = 768.
// ---------------------------------------------------------------------------
__global__ void k_topk(const float* __restrict__ keys) {
    __shared__ float q[DD];
    __shared__ float sims[POOL];

    const int b = blockIdx.x;
    const int t = threadIdx.x;                       // 0..767 (= dim d)
    const int w = t >> 5, lane = t & 31;

    // Sum 32 chunk partials for dim t (coalesced: consecutive t -> consecutive d)
    {
        float s = 0.f;
        #pragma unroll
        for (int c = 0; c < NCHUNK; c++)
            s += g_partial[((size_t)c * BB + b) * DD + t];
        q[t] = s;                                    // unnormalized query
    }
    __syncthreads();

    // Pools: warp w handles p=w (w<24) and p=w+24 (w<8)
    #pragma unroll
    for (int rep = 0; rep < 2; rep++) {
        const int p = w + rep * 24;
        if ((rep == 0) || (w < 8)) {
            float aqk = 0.f, akk = 0.f;
            #pragma unroll
            for (int d = lane; d < DD; d += 32) {
                const float k = keys[(size_t)p * DD + d];
                aqk += q[d] * k;
                akk += k * k;
            }
            #pragma unroll
            for (int o = 16; o > 0; o >>= 1) {
                aqk += __shfl_xor_sync(0xffffffffu, aqk, o);
                akk += __shfl_xor_sync(0xffffffffu, akk, o);
            }
            if (lane == 0)
                sims[p] = aqk * rsqrtf(akk + EPSV);  // q-norm factor dropped
        }
    }
    __syncthreads();

    // Serial top-4 (32 elems): strict > keeps lowest index on ties
    if (t == 0) {
        unsigned used = 0;
        #pragma unroll
        for (int k = 0; k < TOPK; k++) {
            float best = -3.402823e38f; int bi = 0;
            for (int p = 0; p < POOL; p++) {
                if (!((used >> p) & 1u) && sims[p] > best) { best = sims[p]; bi = p; }
            }
            used |= 1u << bi;
            g_topidx[b * TOPK + k] = bi;
        }
    }
}

// ---------------------------------------------------------------------------
// Kernel 3: write the 32 e-prompt rows per batch (rows 8..39).
// grid = (32, BB), block = 192
// ---------------------------------------------------------------------------
__global__ void k_eprompts(const float4* __restrict__ ep,
                           float4* __restrict__ out) {
    const int b  = blockIdx.y;
    const int rr = blockIdx.x;       // 0..31
    const int t  = threadIdx.x;

    const int idx = g_topidx[b * TOPK + (rr >> 3)];   // rr / L
    const float4* src = ep + ((size_t)idx * LL + (rr & 7)) * DD4;
    out[((size_t)b * ROWS_OUT + LL + rr) * DD4 + t] = src[t];
}

// ---------------------------------------------------------------------------
extern "C" void kernel_launch(void* const* d_in, const int* in_sizes, int n_in,
                              void* d_out, int out_size) {
    const float4* x   = (const float4*)d_in[0];   // [64,2048,768]
    const float4* gp  = (const float4*)d_in[1];   // [10,8,768]
    const float4* ep  = (const float4*)d_in[2];   // [32,8,768]
    const float*  key = (const float*) d_in[3];   // [32,768]
    const float4* cls = (const float4*)d_in[4];   // [1,1,768]
    const int*    tid = (const int*)   d_in[5];   // scalar task_id
    float4* out = (float4*)d_out;

    k_copy_reduce<<<dim3(NCHUNK, BB), 192>>>(x, gp, cls, tid, out);
    k_topk<<<BB, 768>>>(key);
    k_eprompts<<<dim3(POOL, BB), 192>>>(ep, out);
}

// round 7
// speedup vs baseline: 1.0619x; 1.0425x over previous
#include <cuda_runtime.h>

// Problem constants (fixed by the reference setup_inputs)
#define BB 64
#define SS 2048
#define DD 768
#define DD4 192          // DD / 4 (float4)
#define POOL 32
#define LL 8
#define TOPK 4
#define PROMPT_ROWS 41   // L + TOPK*L + 1
#define ROWS_OUT 2089    // PROMPT_ROWS + SS
#define SCHUNK 64
#define NCHUNK 32        // SS / SCHUNK -> grid 2048 (measured-best config)
#define EPSV 1e-12f

// Scratch (no allocations allowed in kernel_launch)
__device__ float g_partial[NCHUNK * BB * DD];   // ~6.3 MB

// ---------------------------------------------------------------------------
// Kernel 1: stream-copy x -> out tail, fused with per-(chunk,b,d) partial
// sums. EXACT R1 configuration (measured 119.4us @ 80.6% DRAM). Do not touch.
// grid = (NCHUNK, BB) = 2048 blocks, block = 192 threads.
// ---------------------------------------------------------------------------
__global__ void k_copy_reduce(const float4* __restrict__ x,
                              float4* __restrict__ out) {
    const int b     = blockIdx.y;
    const int chunk = blockIdx.x;
    const int d4    = threadIdx.x;                   // 0..191

    const float4* xp = x   + ((size_t)b * SS + (size_t)chunk * SCHUNK) * DD4 + d4;
    float4*       op = out + ((size_t)b * ROWS_OUT + PROMPT_ROWS
                              + (size_t)chunk * SCHUNK) * DD4 + d4;

    float4 acc = make_float4(0.f, 0.f, 0.f, 0.f);
    #pragma unroll 8
    for (int s = 0; s < SCHUNK; s++) {
        float4 v = xp[(size_t)s * DD4];
        op[(size_t)s * DD4] = v;
        acc.x += v.x; acc.y += v.y; acc.z += v.z; acc.w += v.w;
    }
    ((float4*)g_partial)[((size_t)chunk * BB + b) * DD4 + d4] = acc;
}

// ---------------------------------------------------------------------------
// Kernel 2 (only other node): per batch — reduce partials, sims (q-norm
// dropped: positive per-batch factor cannot change ordering), warp-parallel
// top-4, write all 41 prompt rows.  grid = BB, block = 1024.
// ---------------------------------------------------------------------------
__global__ void k_topk_prompts(const float* __restrict__ keys,
                               const float4* __restrict__ gp,
                               const float4* __restrict__ ep,
                               const float4* __restrict__ cls,
                               const int* __restrict__ task_id,
                               float4* __restrict__ out) {
    __shared__ float q[DD];
    __shared__ float sims[POOL];
    __shared__ int   topidx[TOPK];

    const int b = blockIdx.x;
    const int t = threadIdx.x;
    const int w = t >> 5, lane = t & 31;

    // Unnormalized query: sum 32 chunk partials per dim (coalesced, L2-hot)
    if (t < DD) {
        float s = 0.f;
        #pragma unroll
        for (int c = 0; c < NCHUNK; c++)
            s += g_partial[((size_t)c * BB + b) * DD + t];
        q[t] = s;
    }
    __syncthreads();

    // 32 warps, one pool each: sims[p] = (q . k_p) * rsqrt(||k_p||^2 + eps)
    {
        float aqk = 0.f, akk = 0.f;
        #pragma unroll
        for (int d = lane; d < DD; d += 32) {
            const float k = keys[(size_t)w * DD + d];
            aqk += q[d] * k;
            akk += k * k;
        }
        #pragma unroll
        for (int o = 16; o > 0; o >>= 1) {
            aqk += __shfl_xor_sync(0xffffffffu, aqk, o);
            akk += __shfl_xor_sync(0xffffffffu, akk, o);
        }
        if (lane == 0) sims[w] = aqk * rsqrtf(akk + EPSV);
    }
    __syncthreads();

    // Warp 0: top-4 via warp argmax (desc, lowest index on tie)
    if (w == 0) {
        float v = sims[lane];
        #pragma unroll
        for (int k = 0; k < TOPK; k++) {
            float bv = v; int bi = lane;
            #pragma unroll
            for (int o = 16; o > 0; o >>= 1) {
                const float ov = __shfl_xor_sync(0xffffffffu, bv, o);
                const int   oi = __shfl_xor_sync(0xffffffffu, bi, o);
                if (ov > bv || (ov == bv && oi < bi)) { bv = ov; bi = oi; }
            }
            if (lane == 0) topidx[k] = bi;
            if (lane == bi) v = -3.402823e38f;   // remove winner
        }
    }
    __syncthreads();

    // Write all 41 prompt rows for this batch (7872 float4, ~8/thread)
    const int task = task_id[0];
    float4* ob = out + (size_t)b * ROWS_OUT * DD4;
    for (int idx = t; idx < PROMPT_ROWS * DD4; idx += 1024) {
        const int r  = idx / DD4;
        const int d4 = idx - r * DD4;
        const float4* src;
        if (r < LL) {
            src = gp + ((size_t)task * LL + r) * DD4;
        } else if (r < LL + TOPK * LL) {
            const int rr = r - LL;
            src = ep + ((size_t)topidx[rr >> 3] * LL + (rr & 7)) * DD4;
        } else {
            src = cls;
        }
        ob[(size_t)r * DD4 + d4] = src[d4];
    }
}

// ---------------------------------------------------------------------------
extern "C" void kernel_launch(void* const* d_in, const int* in_sizes, int n_in,
                              void* d_out, int out_size) {
    const float4* x   = (const float4*)d_in[0];   // [64,2048,768]
    const float4* gp  = (const float4*)d_in[1];   // [10,8,768]
    const float4* ep  = (const float4*)d_in[2];   // [32,8,768]
    const float*  key = (const float*) d_in[3];   // [32,768]
    const float4* cls = (const float4*)d_in[4];   // [1,1,768]
    const int*    tid = (const int*)   d_in[5];   // scalar task_id
    float4* out = (float4*)d_out;

    k_copy_reduce<<<dim3(NCHUNK, BB), 192>>>(x, out);
    k_topk_prompts<<<BB, 1024>>>(key, gp, ep, cls, tid, out);
}